// round 10
// baseline (speedup 1.0000x reference)
#include <cuda_runtime.h>

#define B_ROWS 8192
#define D_DIM  128
#define C_CLS  100
#define MARGIN 0.3f
#define NBLK   1024   // 8 warps/block, 1 row per warp

__device__ float        g_accum;  // zero at load; reset by last block each run
__device__ unsigned int g_done;   // zero at load; reset by last block each run

__global__ __launch_bounds__(256)
void triplet_fused_kernel(const float* __restrict__ x,
                          const void*  __restrict__ targets,
                          const void*  __restrict__ ixs,
                          const float* __restrict__ brdf,
                          float*       __restrict__ out) {
    const int warp = threadIdx.x >> 5;
    const int lane = threadIdx.x & 31;
    const int row  = blockIdx.x * 8 + warp;   // grid exactly covers B_ROWS

    // ---------- trip 1: independent, bounds-safe-for-both-widths loads ----------
    unsigned int hw = ((const unsigned int*)targets)[2 * lane + 1];  // int64 LE => odd words zero
    int2 w32 = ((const int2*)ixs)[row];       // int32 view of ixs[row] (in-bounds either width)
    float4 a = ((const float4*)(x + (size_t)row * D_DIM))[lane];
    int tb = ((const int*)targets)[row];      // int32 interpretation

    const int is64 = (__ballot_sync(0xFFFFFFFFu, hw != 0u) == 0u);

    int i0 = w32.x;
    int i1 = w32.y;
    if (is64) {   // warp-uniform branch; only taken when buffers really are int64
        i0 = (int)((const long long*)ixs)[2 * row];
        i1 = (int)((const long long*)ixs)[2 * row + 1];
        tb = (int)((const long long*)targets)[row];
    }

    // ---------- trip 2: everything else, all concurrent ----------
    float4 p0 = ((const float4*)(x + (size_t)i0 * D_DIM))[lane];
    float4 p1 = ((const float4*)(x + (size_t)i1 * D_DIM))[lane];
    int t0 = is64 ? (int)((const long long*)targets)[i0] : ((const int*)targets)[i0];
    int t1 = is64 ? (int)((const long long*)targets)[i1] : ((const int*)targets)[i1];
    // speculative prefetch of the whole brdf row tb (400B = 25 float4, 16B-aligned):
    float4 brow = make_float4(0.f, 0.f, 0.f, 0.f);
    if (lane < 25) brow = ((const float4*)(brdf + tb * C_CLS))[lane];

    // ---------- compute (no third memory trip) ----------
    float dx, s0, s1;
    dx = a.x - p0.x; s0  = dx * dx;
    dx = a.y - p0.y; s0 += dx * dx;
    dx = a.z - p0.z; s0 += dx * dx;
    dx = a.w - p0.w; s0 += dx * dx;
    dx = a.x - p1.x; s1  = dx * dx;
    dx = a.y - p1.y; s1 += dx * dx;
    dx = a.z - p1.z; s1 += dx * dx;
    dx = a.w - p1.w; s1 += dx * dx;

    #pragma unroll
    for (int off = 16; off > 0; off >>= 1) {
        s0 += __shfl_xor_sync(0xFFFFFFFFu, s0, off);
        s1 += __shfl_xor_sync(0xFFFFFFFFu, s1, off);
    }

    // md1 = brdf[tb, t0], md2 = brdf[tb, t1] via register shuffles (t0,t1 warp-uniform)
    float4 v0 = make_float4(__shfl_sync(0xFFFFFFFFu, brow.x, t0 >> 2),
                            __shfl_sync(0xFFFFFFFFu, brow.y, t0 >> 2),
                            __shfl_sync(0xFFFFFFFFu, brow.z, t0 >> 2),
                            __shfl_sync(0xFFFFFFFFu, brow.w, t0 >> 2));
    float4 v1 = make_float4(__shfl_sync(0xFFFFFFFFu, brow.x, t1 >> 2),
                            __shfl_sync(0xFFFFFFFFu, brow.y, t1 >> 2),
                            __shfl_sync(0xFFFFFFFFu, brow.z, t1 >> 2),
                            __shfl_sync(0xFFFFFFFFu, brow.w, t1 >> 2));
    int c0 = t0 & 3, c1 = t1 & 3;
    float md1 = (c0 == 0) ? v0.x : (c0 == 1) ? v0.y : (c0 == 2) ? v0.z : v0.w;
    float md2 = (c1 == 0) ? v1.x : (c1 == 1) ? v1.y : (c1 == 2) ? v1.z : v1.w;

    float d0 = sqrtf(fmaxf(s0, 1e-12f));
    float d1 = sqrtf(fmaxf(s1, 1e-12f));
    float diff = (md1 < md2) ? (d0 - d1) : (d1 - d0);
    float hinge = fmaxf(diff + MARGIN, 0.0f);

    __shared__ float wsum[8];
    __shared__ int   s_last;
    if (lane == 0) wsum[warp] = hinge;
    __syncthreads();

    if (threadIdx.x == 0) {
        float t = 0.0f;
        #pragma unroll
        for (int w = 0; w < 8; w++) t += wsum[w];
        atomicAdd(&g_accum, t);
        __threadfence();
        unsigned int prev = atomicAdd(&g_done, 1u);
        s_last = (prev == (unsigned int)(gridDim.x - 1));
    }
    __syncthreads();

    if (s_last && threadIdx.x == 0) {
        float total = g_accum;   // all adds visible: g_done hit gridDim after fences
        out[0] = total * (1.0f / (float)B_ROWS);
        g_accum = 0.0f;          // reset for next graph replay
        __threadfence();
        g_done = 0u;
    }
}

extern "C" void kernel_launch(void* const* d_in, const int* in_sizes, int n_in,
                              void* d_out, int out_size) {
    const float* x       = (const float*)d_in[0];  // inputs   [8192,128] f32
    const void*  targets = d_in[1];                // targets  [8192]     i32/i64
    const void*  ixs     = d_in[2];                // ixs      [8192,2]   i32/i64
    const float* brdf    = (const float*)d_in[3];  // brdf     [100,100]  f32
    float*       out     = (float*)d_out;

    triplet_fused_kernel<<<NBLK, 256>>>(x, targets, ixs, brdf, out);
}

// round 12
// speedup vs baseline: 1.2647x; 1.2647x over previous
#include <cuda_runtime.h>

#define B_ROWS 8192
#define D_DIM  128
#define C_CLS  100
#define MARGIN 0.3f
#define NBLK   1024   // 8 warps/block, 1 row per warp

__device__ float        g_accum;  // zero at load; reset by last block each run
__device__ unsigned int g_done;   // zero at load; reset by last block each run

__global__ __launch_bounds__(256)
void triplet_fused_kernel(const float* __restrict__ x,
                          const void*  __restrict__ targets,
                          const void*  __restrict__ ixs,
                          const float* __restrict__ brdf,
                          float*       __restrict__ out) {
    const int warp = threadIdx.x >> 5;
    const int lane = threadIdx.x & 31;
    const int row  = blockIdx.x * 8 + warp;   // grid exactly covers B_ROWS

    // ---------- trip 1: independent, bounds-safe-for-both-widths loads ----------
    unsigned int hw = ((const unsigned int*)targets)[2 * lane + 1];  // int64 LE => odd words zero
    int2 w32 = ((const int2*)ixs)[row];       // int32 view of ixs[row] (in-bounds either width)
    float4 a = ((const float4*)(x + (size_t)row * D_DIM))[lane];
    int tb = ((const int*)targets)[row];      // int32 interpretation

    const int is64 = (__ballot_sync(0xFFFFFFFFu, hw != 0u) == 0u);

    int i0 = w32.x;
    int i1 = w32.y;
    if (is64) {   // warp-uniform branch; only taken when buffers really are int64
        i0 = (int)((const long long*)ixs)[2 * row];
        i1 = (int)((const long long*)ixs)[2 * row + 1];
        tb = (int)((const long long*)targets)[row];
    }

    // ---------- trip 2: all remaining loads concurrent ----------
    float4 p0 = ((const float4*)(x + (size_t)i0 * D_DIM))[lane];
    float4 p1 = ((const float4*)(x + (size_t)i1 * D_DIM))[lane];
    int t0 = is64 ? (int)((const long long*)targets)[i0] : ((const int*)targets)[i0];
    int t1 = is64 ? (int)((const long long*)targets)[i1] : ((const int*)targets)[i1];
    // speculative prefetch of brdf row tb (400B = 25 float4, 16B-aligned)
    float4 brow = make_float4(0.f, 0.f, 0.f, 0.f);
    if (lane < 25) brow = ((const float4*)(brdf + tb * C_CLS))[lane];

    // ---------- compute (no third memory trip) ----------
    float dx, s0, s1;
    dx = a.x - p0.x; s0  = dx * dx;
    dx = a.y - p0.y; s0 += dx * dx;
    dx = a.z - p0.z; s0 += dx * dx;
    dx = a.w - p0.w; s0 += dx * dx;
    dx = a.x - p1.x; s1  = dx * dx;
    dx = a.y - p1.y; s1 += dx * dx;
    dx = a.z - p1.z; s1 += dx * dx;
    dx = a.w - p1.w; s1 += dx * dx;

    #pragma unroll
    for (int off = 16; off > 0; off >>= 1) {
        s0 += __shfl_xor_sync(0xFFFFFFFFu, s0, off);
        s1 += __shfl_xor_sync(0xFFFFFFFFu, s1, off);
    }

    // md1 = brdf[tb, t0], md2 = brdf[tb, t1] via register shuffles (t0,t1 warp-uniform)
    float4 v0 = make_float4(__shfl_sync(0xFFFFFFFFu, brow.x, t0 >> 2),
                            __shfl_sync(0xFFFFFFFFu, brow.y, t0 >> 2),
                            __shfl_sync(0xFFFFFFFFu, brow.z, t0 >> 2),
                            __shfl_sync(0xFFFFFFFFu, brow.w, t0 >> 2));
    float4 v1 = make_float4(__shfl_sync(0xFFFFFFFFu, brow.x, t1 >> 2),
                            __shfl_sync(0xFFFFFFFFu, brow.y, t1 >> 2),
                            __shfl_sync(0xFFFFFFFFu, brow.z, t1 >> 2),
                            __shfl_sync(0xFFFFFFFFu, brow.w, t1 >> 2));
    int c0 = t0 & 3, c1 = t1 & 3;
    float md1 = (c0 == 0) ? v0.x : (c0 == 1) ? v0.y : (c0 == 2) ? v0.z : v0.w;
    float md2 = (c1 == 0) ? v1.x : (c1 == 1) ? v1.y : (c1 == 2) ? v1.z : v1.w;

    float d0 = sqrtf(fmaxf(s0, 1e-12f));
    float d1 = sqrtf(fmaxf(s1, 1e-12f));
    float diff = (md1 < md2) ? (d0 - d1) : (d1 - d0);
    float hinge = fmaxf(diff + MARGIN, 0.0f);

    __shared__ float wsum[8];
    if (lane == 0) wsum[warp] = hinge;
    __syncthreads();

    // ---------- fence-free tail: release-add on counter, acquire by last block ----------
    if (threadIdx.x == 0) {
        float t = 0.0f;
        #pragma unroll
        for (int w = 0; w < 8; w++) t += wsum[w];
        atomicAdd(&g_accum, t);                 // device-scope float add (L2-serialized)
        unsigned int prev;
        asm volatile("atom.acq_rel.gpu.global.add.u32 %0, [%1], %2;"
                     : "=r"(prev) : "l"(&g_done), "r"(1u) : "memory");
        if (prev == (unsigned int)(NBLK - 1)) {
            // acq_rel above orders this read after all blocks' release-adds
            float total = g_accum;
            out[0] = total * (1.0f / (float)B_ROWS);
            g_accum = 0.0f;                     // reset for next graph replay
            g_done  = 0u;                       // kernel boundary orders vs next launch
        }
    }
}

extern "C" void kernel_launch(void* const* d_in, const int* in_sizes, int n_in,
                              void* d_out, int out_size) {
    const float* x       = (const float*)d_in[0];  // inputs   [8192,128] f32
    const void*  targets = d_in[1];                // targets  [8192]     i32/i64
    const void*  ixs     = d_in[2];                // ixs      [8192,2]   i32/i64
    const float* brdf    = (const float*)d_in[3];  // brdf     [100,100]  f32
    float*       out     = (float*)d_out;

    triplet_fused_kernel<<<NBLK, 256>>>(x, targets, ixs, brdf, out);
}